// round 15
// baseline (speedup 1.0000x reference)
#include <cuda_runtime.h>
#include <cuda_fp16.h>
#include <cstdint>

// Shapes (fixed):
//  x1  [2,64,8,8,8,8]   x2 [2,32,16,16,16,16]
//  up_w[64,32,2,2,2,2]  up_b[32]
//  w1  [32,64,3,3,3,3]  b1[32]
//  w2  [32,32,3,3,3,3]  b2[32]
//  w3  [32,64]          b3[32]
//  out [2,32,16,16,16,16] fp32
//
// Implicit GEMM, mma.sync.m16n8k16 fp16 single-pass (fp32 accum).
// CTA = full (b,t,d) plane (M=256), 128 threads, 4 warps x m64.
// Stage = (kt,kd) x ci-16-slice; kh,kw are address shifts into one staged
// 18x18 channel-sliced plane. KC=16 keeps smem at 39KB -> 3 CTAs/SM.
// Fragments loaded via ldmatrix.x4 (6 issues/bundle vs 24 scalar LDS).
// Smem rows are 32B slots, 4-per-128B-line, 16B parity rotation (conflict-free).

#define F18 104976   // 18^4
#define C18 5832     // 18^3
#define S18 324      // 18^2

// ---- scratch (device globals; zero-initialized at module load — halos are
// never written, interiors fully rewritten every call) ----
__device__ __half g_xcF[2 * F18 * 64];
__device__ __half g_y1F[2 * F18 * 32];
__device__ __half g_w1F[81 * 32 * 64];
__device__ __half g_w2F[81 * 32 * 32];
__device__ __half g_w3F[2 * 32 * 32];

// ---- helpers ----
__device__ __forceinline__ uint32_t smem_u32(const void* p) {
    return (uint32_t)__cvta_generic_to_shared(p);
}
__device__ __forceinline__ void cp16(uint32_t dst, const void* src) {
    asm volatile("cp.async.cg.shared.global [%0], [%1], 16;" :: "r"(dst), "l"(src) : "memory");
}
#define CP_COMMIT() asm volatile("cp.async.commit_group;" ::: "memory")
#define CP_WAIT1()  asm volatile("cp.async.wait_group 1;"  ::: "memory")

__device__ __forceinline__ void mma_fp16(float* d, const uint32_t* a, const uint32_t* b) {
    asm volatile(
        "mma.sync.aligned.m16n8k16.row.col.f32.f16.f16.f32 "
        "{%0,%1,%2,%3}, {%4,%5,%6,%7}, {%8,%9}, {%0,%1,%2,%3};"
        : "+f"(d[0]), "+f"(d[1]), "+f"(d[2]), "+f"(d[3])
        : "r"(a[0]), "r"(a[1]), "r"(a[2]), "r"(a[3]), "r"(b[0]), "r"(b[1]));
}
// ldmatrix x4: 4 8x8 fp16 matrices; lane groups of 8 supply row addresses.
__device__ __forceinline__ void ldsm4(uint32_t* r, uint32_t addr) {
    asm volatile("ldmatrix.sync.aligned.m8n8.x4.shared.b16 {%0,%1,%2,%3}, [%4];"
                 : "=r"(r[0]), "=r"(r[1]), "=r"(r[2]), "=r"(r[3]) : "r"(addr));
}
__device__ __forceinline__ uint32_t pack_hf(__half a, __half b) {
    return (uint32_t)__half_as_ushort(a) | ((uint32_t)__half_as_ushort(b) << 16);
}
// 32B-slot smem offset: row pr (32B of data), byte o in slot (0..31).
// 4 slots per 128B line; 16B rotation by line parity -> conflict-free.
__device__ __forceinline__ uint32_t sl32(int pr, int o) {
    return (uint32_t)(((pr >> 2) << 7) + ((pr & 3) << 5) + ((o + (((pr >> 2) & 1) << 4)) & 31));
}

// ---------------------------------------------------------------------------
// Prep kernels
// ---------------------------------------------------------------------------
// upsample x1 + concat with x2 -> padded channels-last xc (fp16)
__global__ __launch_bounds__(256) void pack_kernel(
    const float* __restrict__ x1, const float* __restrict__ x2,
    const float* __restrict__ uw, const float* __restrict__ ub)
{
    int bx = blockIdx.x;
    int b = bx >> 8, t = (bx >> 4) & 15, d = bx & 15;
    int tid = threadIdx.x;
    int h = tid >> 4, w = tid & 15;

    float acc[32];
#pragma unroll
    for (int co = 0; co < 32; co++) acc[co] = ub[co];

    int sub = ((t & 1) << 3) | ((d & 1) << 2) | ((h & 1) << 1) | (w & 1);
    const float* xp = x1 + (((size_t)b * 64) << 12) + ((t >> 1) << 9) + ((d >> 1) << 6) + ((h >> 1) << 3) + (w >> 1);
#pragma unroll 4
    for (int ci = 0; ci < 64; ci++) {
        float xv = xp[(size_t)ci << 12];
        const float* wr = uw + ((size_t)ci << 9) + sub;
#pragma unroll
        for (int co = 0; co < 32; co++) acc[co] += xv * wr[co << 4];
    }

    size_t ridx = (size_t)b * F18 + (size_t)(t + 1) * C18 + (d + 1) * S18 + (h + 1) * 18 + (w + 1);
    uint32_t row[32];
    int pos = (t << 12) + (d << 8) + (h << 4) + w;
#pragma unroll
    for (int c = 0; c < 16; c++) {
        float v0 = x2[(((size_t)(b * 32 + 2 * c)) << 16) + pos];
        float v1 = x2[(((size_t)(b * 32 + 2 * c + 1)) << 16) + pos];
        row[c] = pack_hf(__float2half_rn(v0), __float2half_rn(v1));
    }
#pragma unroll
    for (int c = 0; c < 16; c++) {
        row[16 + c] = pack_hf(__float2half_rn(acc[2 * c]), __float2half_rn(acc[2 * c + 1]));
    }
    uint4* of = (uint4*)(g_xcF + ridx * 64);
#pragma unroll
    for (int q = 0; q < 8; q++)
        of[q] = make_uint4(row[4 * q], row[4 * q + 1], row[4 * q + 2], row[4 * q + 3]);
}

// weights -> [tap81][co][ci] fp16 (rounded once)
__global__ void wprep_kernel(const float* __restrict__ w1, const float* __restrict__ w2,
                             const float* __restrict__ w3)
{
    int i = blockIdx.x * blockDim.x + threadIdx.x;
    int stride = gridDim.x * blockDim.x;
    for (; i < 81 * 32 * 64 + 81 * 32 * 32 + 2 * 32 * 32; i += stride) {
        if (i < 81 * 32 * 64) {
            int tp = i >> 11, rem = i & 2047;
            int co = rem >> 6, ci = rem & 63;
            g_w1F[i] = __float2half_rn(w1[((size_t)(co * 64 + ci)) * 81 + tp]);
        } else if (i < 81 * 32 * 64 + 81 * 32 * 32) {
            int j = i - 81 * 32 * 64;
            int tp = j >> 10, rem = j & 1023;
            int co = rem >> 5, ci = rem & 31;
            g_w2F[j] = __float2half_rn(w2[((size_t)(co * 32 + ci)) * 81 + tp]);
        } else {
            int k = i - 81 * 32 * 64 - 81 * 32 * 32;
            int half_ = k >> 10, rem = k & 1023;
            int co = rem >> 5, ci = rem & 31;
            g_w3F[k] = __float2half_rn(w3[co * 64 + half_ * 32 + ci]);
        }
    }
}

// ---------------------------------------------------------------------------
// Conv kernel. M=256 plane per (b,t,d), 4 warps x m64, N=32, KC=16/stage.
//  CONV=1: stages = (kt,kd) x ci-quarter = 36; A = xc 16-ch slice; B = w1 slice.
//  CONV=2: stages = (kt,kd) x ci-half = 18 over y1 + 4 skip stages (xc quarters * w3).
// A plane/stage: 324 rows x 16ch fp16 (32B rows). B: 9 taps x 32 co x 32B.
// ---------------------------------------------------------------------------
template <int CONV>
__global__ __launch_bounds__(128, 3) void conv_mma(
    const __half* __restrict__ aF,
    const __half* __restrict__ wF,
    const __half* __restrict__ sF,
    const __half* __restrict__ w3F,
    const float* __restrict__ bias0, const float* __restrict__ bias1,
    __half* __restrict__ outH,
    float* __restrict__ outF)
{
    constexpr int NS   = (CONV == 1) ? 36 : 22;
    constexpr int NMAIN= (CONV == 1) ? 36 : 18;
    constexpr int APL  = 324 * 32;            // 10368 B A plane
    constexpr int BB   = 9 * 32 * 32;         // 9216 B
    constexpr int BUF  = APL + BB;            // 19584
    constexpr int ACH  = 324 * 2;             // A 16B chunks = 648
    constexpr int CHT  = ACH + 9 * 32 * 2;    // 1224 chunk slots
    constexpr int WROW = (CONV == 1) ? 64 : 32;  // ci stride per co row in gmem
    constexpr int TAPS = 32 * WROW;
    constexpr int QSH  = (CONV == 1) ? 2 : 1;    // log2(slices per (kt,kd))
    constexpr int QMSK = (CONV == 1) ? 3 : 1;

    extern __shared__ __align__(128) char smem[];
    uint32_t sb0 = smem_u32(smem);

    int bx  = blockIdx.x;
    int t   = bx >> 4, d = bx & 15;
    int b   = blockIdx.y;
    int tid = threadIdx.x;
    int wid = tid >> 5;
    int lane = tid & 31;
    int lr = lane >> 2, lc = lane & 3;
    size_t bOff = (size_t)b * F18;

    // ldmatrix per-lane address constants
    int lsub  = lane >> 3, l8 = lane & 7;
    int rofsA = l8 + ((lsub & 1) << 3);      // A: row offset within m16 tile
    int oA    = (lsub >> 1) << 4;            // A: slot byte (k halves)
    int rofsB = l8 + ((lsub >> 1) << 3);     // B: co row offset within n16 group
    int oB    = (lsub & 1) << 4;             // B: slot byte (k halves)

    float acc[4][4][4];
#pragma unroll
    for (int mt = 0; mt < 4; mt++)
#pragma unroll
        for (int j = 0; j < 4; j++)
#pragma unroll
            for (int e = 0; e < 4; e++) acc[mt][j][e] = 0.f;

    // ---- stage copy (all 128 threads) ----
    auto stage_copy = [&](int s, int bufi) {
        int kt, kd, chbase, srcch, ntap;
        const __half *src_, *wsrc;
        if (CONV == 2 && s >= 18) {
            int q = s - 18;                    // xc quarter 0..3
            kt = 1; kd = 1;
            src_ = sF; srcch = 64; chbase = q << 4;
            wsrc = w3F + ((q >> 1) << 10) + ((q & 1) << 4);
            ntap = 1;
        } else {
            int pair = s >> QSH;
            int q    = s & QMSK;
            kt = pair / 3; kd = pair % 3;
            src_ = aF;
            srcch = (CONV == 1) ? 64 : 32;
            chbase = q << 4;
            wsrc = wF + (size_t)(kt * 27 + kd * 9) * TAPS + chbase;
            ntap = 9;
        }
        uint32_t sb = sb0 + (uint32_t)bufi * BUF;
        size_t abase = bOff + (size_t)(t + kt) * C18 + (size_t)(d + kd) * S18;
#pragma unroll
        for (int ii = 0; ii < 10; ii++) {
            int i = tid + ii * 128;
            if (i < ACH) {
                int pr = i >> 1, c = i & 1;
                const __half* g = src_ + (abase + pr) * srcch + chbase + c * 8;
                cp16(sb + sl32(pr, c << 4), g);
            } else if (i < CHT) {
                int j2 = i - ACH;
                int tt = j2 >> 6;
                int e  = j2 & 63;
                int r  = e >> 1, c = e & 1;
                if (tt < ntap) {
                    const __half* g = wsrc + (size_t)tt * TAPS + r * WROW + c * 8;
                    cp16(sb + APL + sl32((tt << 5) + r, c << 4), g);
                }
            }
        }
    };

    // ---- compute bundle: one (kh,kw) tap, 4 mt x 4 j, single k16 ----
    // A fragments: 4x ldmatrix.x4 (matrices: m0-7/k0-7, m8-15/k0-7, m0-7/k8-15, m8-15/k8-15)
    // B fragments: 2x ldmatrix.x4 (n0-7/k0-7, n0-7/k8-15, n8-15/k0-7, n8-15/k8-15)
    auto bundle = [&](uint32_t Ab, uint32_t Bb, int kh, int kw, int tb) {
        uint32_t af[4][4];
#pragma unroll
        for (int mt = 0; mt < 4; mt++) {
            int pr = (4 * wid + mt + kh) * 18 + kw + rofsA;
            ldsm4(af[mt], Ab + sl32(pr, oA));
        }
        uint32_t b01[4], b23[4];
        int prB = (tb << 5) + rofsB;
        ldsm4(b01, Bb + sl32(prB, oB));          // j=0 (b0,b1), j=1 (b0,b1)
        ldsm4(b23, Bb + sl32(prB + 16, oB));     // j=2, j=3
#pragma unroll
        for (int mt = 0; mt < 4; mt++) {
            mma_fp16(acc[mt][0], af[mt], b01 + 0);
            mma_fp16(acc[mt][1], af[mt], b01 + 2);
            mma_fp16(acc[mt][2], af[mt], b23 + 0);
            mma_fp16(acc[mt][3], af[mt], b23 + 2);
        }
    };

    stage_copy(0, 0);
    CP_COMMIT();

#pragma unroll 1
    for (int s = 0; s < NS; s++) {
        __syncthreads();                 // compute(s-1) done -> buffer (s+1)&1 free
        if (s + 1 < NS) stage_copy(s + 1, (s + 1) & 1);
        CP_COMMIT();
        CP_WAIT1();                      // stage s deposits landed (this thread)
        __syncthreads();                 // all deposits visible

        uint32_t Ab = sb0 + (uint32_t)((s & 1) * BUF);
        uint32_t Bb = Ab + APL;

        if (CONV == 2 && s >= NMAIN) {
            bundle(Ab, Bb, 1, 1, 0);
        } else {
#pragma unroll
            for (int kh = 0; kh < 3; kh++)
#pragma unroll
                for (int kw = 0; kw < 3; kw++)
                    bundle(Ab, Bb, kh, kw, kh * 3 + kw);
        }
    }

    // ---- epilogue ----
    float bb0[4], bb1[4];
#pragma unroll
    for (int j = 0; j < 4; j++) {
        int co = 8 * j + 2 * lc;
        bb0[j] = bias0[co]     + ((CONV == 2) ? bias1[co]     : 0.f);
        bb1[j] = bias0[co + 1] + ((CONV == 2) ? bias1[co + 1] : 0.f);
    }

#pragma unroll
    for (int mt = 0; mt < 4; mt++) {
        int h = 4 * wid + mt;
#pragma unroll
        for (int rr = 0; rr < 2; rr++) {
            int w = lr + 8 * rr;
            if (CONV == 1) {
                size_t ridx = bOff + (size_t)(t + 1) * C18 + (d + 1) * S18 + (h + 1) * 18 + (w + 1);
                uint32_t* oh = (uint32_t*)(outH + ridx * 32);
#pragma unroll
                for (int j = 0; j < 4; j++) {
                    float v0 = fmaxf(acc[mt][j][rr * 2 + 0] + bb0[j], 0.f);
                    float v1 = fmaxf(acc[mt][j][rr * 2 + 1] + bb1[j], 0.f);
                    oh[4 * j + lc] = pack_hf(__float2half_rn(v0), __float2half_rn(v1));
                }
            } else {
                size_t obase = ((size_t)b * 32) << 16;
                int opos = (t << 12) + (d << 8) + (h << 4) + w;
#pragma unroll
                for (int j = 0; j < 4; j++) {
                    int co = 8 * j + 2 * lc;
                    float v0 = fmaxf(acc[mt][j][rr * 2 + 0] + bb0[j], 0.f);
                    float v1 = fmaxf(acc[mt][j][rr * 2 + 1] + bb1[j], 0.f);
                    outF[obase + (((size_t)co) << 16) + opos]       = v0;
                    outF[obase + (((size_t)(co + 1)) << 16) + opos] = v1;
                }
            }
        }
    }
}

// ---------------------------------------------------------------------------
extern "C" void kernel_launch(void* const* d_in, const int* in_sizes, int n_in,
                              void* d_out, int out_size)
{
    const float* x1   = (const float*)d_in[0];
    const float* x2   = (const float*)d_in[1];
    const float* up_w = (const float*)d_in[2];
    const float* up_b = (const float*)d_in[3];
    const float* w1   = (const float*)d_in[4];
    const float* b1   = (const float*)d_in[5];
    const float* w2   = (const float*)d_in[6];
    const float* b2   = (const float*)d_in[7];
    const float* w3   = (const float*)d_in[8];
    const float* b3   = (const float*)d_in[9];
    float* out = (float*)d_out;

    __half *xcF, *y1F, *w1F, *w2F, *w3F;
    cudaGetSymbolAddress((void**)&xcF, g_xcF);
    cudaGetSymbolAddress((void**)&y1F, g_y1F);
    cudaGetSymbolAddress((void**)&w1F, g_w1F);
    cudaGetSymbolAddress((void**)&w2F, g_w2F);
    cudaGetSymbolAddress((void**)&w3F, g_w3F);

    constexpr int SMB = 2 * (324 * 32 + 9 * 32 * 32);  // 39168 bytes
    cudaFuncSetAttribute(conv_mma<1>, cudaFuncAttributeMaxDynamicSharedMemorySize, SMB);
    cudaFuncSetAttribute(conv_mma<2>, cudaFuncAttributeMaxDynamicSharedMemorySize, SMB);

    pack_kernel<<<512, 256>>>(x1, x2, up_w, up_b);
    wprep_kernel<<<512, 256>>>(w1, w2, w3);

    // conv1: y1 = relu(conv(xc, w1) + b1)
    conv_mma<1><<<dim3(256, 2), 128, SMB>>>(
        xcF, w1F, nullptr, nullptr,
        b1, nullptr, y1F, nullptr);

    // conv2: out = relu(conv(y1, w2) + b2 + conv1x1(xc, w3) + b3)
    conv_mma<2><<<dim3(256, 2), 128, SMB>>>(
        y1F, w2F, xcF, w3F,
        b2, b3, nullptr, out);
}

// round 17
// speedup vs baseline: 1.1835x; 1.1835x over previous
#include <cuda_runtime.h>
#include <cuda_fp16.h>
#include <cstdint>

// Shapes (fixed):
//  x1  [2,64,8,8,8,8]   x2 [2,32,16,16,16,16]
//  up_w[64,32,2,2,2,2]  up_b[32]
//  w1  [32,64,3,3,3,3]  b1[32]
//  w2  [32,32,3,3,3,3]  b2[32]
//  w3  [32,64]          b3[32]
//  out [2,32,16,16,16,16] fp32
//
// Implicit GEMM, mma.sync.m16n8k16 fp16 single-pass (fp32 accum).
// CTA = full (b,t,d) plane (M=256), 128 threads, 4 warps x m64.
// Stage = (kt,kd) x ci-16-slice. KC=16, smem 39KB, __launch_bounds__(128,4)
// -> 4 CTAs/SM (16 warps) and single-wave 512-CTA grids.
// Fragments via ldmatrix.x4; 32B-slot smem with 16B parity rotation.

#define F18 104976   // 18^4
#define C18 5832     // 18^3
#define S18 324      // 18^2

// ---- scratch (device globals; zero-initialized at module load — halos are
// never written, interiors fully rewritten every call) ----
__device__ __half g_xcF[2 * F18 * 64];
__device__ __half g_y1F[2 * F18 * 32];
__device__ __half g_w1F[81 * 32 * 64];
__device__ __half g_w2F[81 * 32 * 32];
__device__ __half g_w3F[2 * 32 * 32];

// ---- helpers ----
__device__ __forceinline__ uint32_t smem_u32(const void* p) {
    return (uint32_t)__cvta_generic_to_shared(p);
}
__device__ __forceinline__ void cp16(uint32_t dst, const void* src) {
    asm volatile("cp.async.cg.shared.global [%0], [%1], 16;" :: "r"(dst), "l"(src) : "memory");
}
#define CP_COMMIT() asm volatile("cp.async.commit_group;" ::: "memory")
#define CP_WAIT1()  asm volatile("cp.async.wait_group 1;"  ::: "memory")

__device__ __forceinline__ void mma_fp16(float* d, const uint32_t* a, const uint32_t* b) {
    asm volatile(
        "mma.sync.aligned.m16n8k16.row.col.f32.f16.f16.f32 "
        "{%0,%1,%2,%3}, {%4,%5,%6,%7}, {%8,%9}, {%0,%1,%2,%3};"
        : "+f"(d[0]), "+f"(d[1]), "+f"(d[2]), "+f"(d[3])
        : "r"(a[0]), "r"(a[1]), "r"(a[2]), "r"(a[3]), "r"(b[0]), "r"(b[1]));
}
// ldmatrix x4: 4 8x8 fp16 matrices; lane groups of 8 supply row addresses.
__device__ __forceinline__ void ldsm4(uint32_t* r, uint32_t addr) {
    asm volatile("ldmatrix.sync.aligned.m8n8.x4.shared.b16 {%0,%1,%2,%3}, [%4];"
                 : "=r"(r[0]), "=r"(r[1]), "=r"(r[2]), "=r"(r[3]) : "r"(addr));
}
__device__ __forceinline__ uint32_t pack_hf(__half a, __half b) {
    return (uint32_t)__half_as_ushort(a) | ((uint32_t)__half_as_ushort(b) << 16);
}
// 32B-slot smem offset: row pr (32B of data), byte o in slot (0..31).
// 4 slots per 128B line; 16B rotation by line parity -> conflict-free.
__device__ __forceinline__ uint32_t sl32(int pr, int o) {
    return (uint32_t)(((pr >> 2) << 7) + ((pr & 3) << 5) + ((o + (((pr >> 2) & 1) << 4)) & 31));
}

// ---------------------------------------------------------------------------
// Fused prep kernel: blocks [0,512) = pack (upsample+concat -> xc fp16);
//                    blocks [512,1024) = weight fp16 repack.
// ---------------------------------------------------------------------------
__global__ __launch_bounds__(256) void prep_kernel(
    const float* __restrict__ x1, const float* __restrict__ x2,
    const float* __restrict__ uw, const float* __restrict__ ub,
    const float* __restrict__ w1, const float* __restrict__ w2,
    const float* __restrict__ w3)
{
    int bx = blockIdx.x;
    int tid = threadIdx.x;

    if (bx >= 512) {
        // ---- weight repack ----
        int i = (bx - 512) * 256 + tid;
        int stride = 512 * 256;
        for (; i < 81 * 32 * 64 + 81 * 32 * 32 + 2 * 32 * 32; i += stride) {
            if (i < 81 * 32 * 64) {
                int tp = i >> 11, rem = i & 2047;
                int co = rem >> 6, ci = rem & 63;
                g_w1F[i] = __float2half_rn(w1[((size_t)(co * 64 + ci)) * 81 + tp]);
            } else if (i < 81 * 32 * 64 + 81 * 32 * 32) {
                int j = i - 81 * 32 * 64;
                int tp = j >> 10, rem = j & 1023;
                int co = rem >> 5, ci = rem & 31;
                g_w2F[j] = __float2half_rn(w2[((size_t)(co * 32 + ci)) * 81 + tp]);
            } else {
                int k = i - 81 * 32 * 64 - 81 * 32 * 32;
                int half_ = k >> 10, rem = k & 1023;
                int co = rem >> 5, ci = rem & 31;
                g_w3F[k] = __float2half_rn(w3[co * 64 + half_ * 32 + ci]);
            }
        }
        return;
    }

    // ---- pack: upsample x1 + concat x2 ----
    int b = bx >> 8, t = (bx >> 4) & 15, d = bx & 15;
    int h = tid >> 4, w = tid & 15;

    float acc[32];
#pragma unroll
    for (int co = 0; co < 32; co++) acc[co] = ub[co];

    int sub = ((t & 1) << 3) | ((d & 1) << 2) | ((h & 1) << 1) | (w & 1);
    const float* xp = x1 + (((size_t)b * 64) << 12) + ((t >> 1) << 9) + ((d >> 1) << 6) + ((h >> 1) << 3) + (w >> 1);
#pragma unroll 4
    for (int ci = 0; ci < 64; ci++) {
        float xv = xp[(size_t)ci << 12];
        const float* wr = uw + ((size_t)ci << 9) + sub;
#pragma unroll
        for (int co = 0; co < 32; co++) acc[co] += xv * wr[co << 4];
    }

    size_t ridx = (size_t)b * F18 + (size_t)(t + 1) * C18 + (d + 1) * S18 + (h + 1) * 18 + (w + 1);
    uint32_t row[32];
    int pos = (t << 12) + (d << 8) + (h << 4) + w;
#pragma unroll
    for (int c = 0; c < 16; c++) {
        float v0 = x2[(((size_t)(b * 32 + 2 * c)) << 16) + pos];
        float v1 = x2[(((size_t)(b * 32 + 2 * c + 1)) << 16) + pos];
        row[c] = pack_hf(__float2half_rn(v0), __float2half_rn(v1));
    }
#pragma unroll
    for (int c = 0; c < 16; c++) {
        row[16 + c] = pack_hf(__float2half_rn(acc[2 * c]), __float2half_rn(acc[2 * c + 1]));
    }
    uint4* of = (uint4*)(g_xcF + ridx * 64);
#pragma unroll
    for (int q = 0; q < 8; q++)
        of[q] = make_uint4(row[4 * q], row[4 * q + 1], row[4 * q + 2], row[4 * q + 3]);
}

// ---------------------------------------------------------------------------
// Conv kernel. M=256 plane per (b,t,d), 4 warps x m64, N=32, KC=16/stage.
//  CONV=1: stages = (kt,kd) x ci-quarter = 36; A = xc 16-ch slice; B = w1 slice.
//  CONV=2: stages = (kt,kd) x ci-half = 18 over y1 + 4 skip stages (xc quarters * w3).
// A plane/stage: 324 rows x 16ch fp16 (32B rows). B: 9 taps x 32 co x 32B.
// ---------------------------------------------------------------------------
template <int CONV>
__global__ __launch_bounds__(128, 4) void conv_mma(
    const __half* __restrict__ aF,
    const __half* __restrict__ wF,
    const __half* __restrict__ sF,
    const __half* __restrict__ w3F,
    const float* __restrict__ bias0, const float* __restrict__ bias1,
    __half* __restrict__ outH,
    float* __restrict__ outF)
{
    constexpr int NS   = (CONV == 1) ? 36 : 22;
    constexpr int NMAIN= (CONV == 1) ? 36 : 18;
    constexpr int APL  = 324 * 32;            // 10368 B A plane
    constexpr int BB   = 9 * 32 * 32;         // 9216 B
    constexpr int BUF  = APL + BB;            // 19584
    constexpr int ACH  = 324 * 2;             // A 16B chunks = 648
    constexpr int CHT  = ACH + 9 * 32 * 2;    // 1224 chunk slots
    constexpr int WROW = (CONV == 1) ? 64 : 32;  // ci stride per co row in gmem
    constexpr int TAPS = 32 * WROW;
    constexpr int QSH  = (CONV == 1) ? 2 : 1;    // log2(slices per (kt,kd))
    constexpr int QMSK = (CONV == 1) ? 3 : 1;

    extern __shared__ __align__(128) char smem[];
    uint32_t sb0 = smem_u32(smem);

    int bx  = blockIdx.x;
    int t   = bx >> 4, d = bx & 15;
    int b   = blockIdx.y;
    int tid = threadIdx.x;
    int wid = tid >> 5;
    int lane = tid & 31;
    int lr = lane >> 2, lc = lane & 3;
    size_t bOff = (size_t)b * F18;

    // ldmatrix per-lane address constants
    int lsub  = lane >> 3, l8 = lane & 7;
    int rofsA = l8 + ((lsub & 1) << 3);      // A: row offset within m16 tile
    int oA    = (lsub >> 1) << 4;            // A: slot byte (k halves)
    int rofsB = l8 + ((lsub >> 1) << 3);     // B: co row offset within n16 group
    int oB    = (lsub & 1) << 4;             // B: slot byte (k halves)

    float acc[4][4][4];
#pragma unroll
    for (int mt = 0; mt < 4; mt++)
#pragma unroll
        for (int j = 0; j < 4; j++)
#pragma unroll
            for (int e = 0; e < 4; e++) acc[mt][j][e] = 0.f;

    // ---- stage copy (all 128 threads) ----
    auto stage_copy = [&](int s, int bufi) {
        int kt, kd, chbase, srcch, ntap;
        const __half *src_, *wsrc;
        if (CONV == 2 && s >= 18) {
            int q = s - 18;                    // xc quarter 0..3
            kt = 1; kd = 1;
            src_ = sF; srcch = 64; chbase = q << 4;
            wsrc = w3F + ((q >> 1) << 10) + ((q & 1) << 4);
            ntap = 1;
        } else {
            int pair = s >> QSH;
            int q    = s & QMSK;
            kt = pair / 3; kd = pair % 3;
            src_ = aF;
            srcch = (CONV == 1) ? 64 : 32;
            chbase = q << 4;
            wsrc = wF + (size_t)(kt * 27 + kd * 9) * TAPS + chbase;
            ntap = 9;
        }
        uint32_t sb = sb0 + (uint32_t)bufi * BUF;
        size_t abase = bOff + (size_t)(t + kt) * C18 + (size_t)(d + kd) * S18;
#pragma unroll
        for (int ii = 0; ii < 10; ii++) {
            int i = tid + ii * 128;
            if (i < ACH) {
                int pr = i >> 1, c = i & 1;
                const __half* g = src_ + (abase + pr) * srcch + chbase + c * 8;
                cp16(sb + sl32(pr, c << 4), g);
            } else if (i < CHT) {
                int j2 = i - ACH;
                int tt = j2 >> 6;
                int e  = j2 & 63;
                int r  = e >> 1, c = e & 1;
                if (tt < ntap) {
                    const __half* g = wsrc + (size_t)tt * TAPS + r * WROW + c * 8;
                    cp16(sb + APL + sl32((tt << 5) + r, c << 4), g);
                }
            }
        }
    };

    // ---- compute bundle: one (kh,kw) tap, 4 mt x 4 j, single k16 ----
    auto bundle = [&](uint32_t Ab, uint32_t Bb, int kh, int kw, int tb) {
        uint32_t af[4][4];
#pragma unroll
        for (int mt = 0; mt < 4; mt++) {
            int pr = (4 * wid + mt + kh) * 18 + kw + rofsA;
            ldsm4(af[mt], Ab + sl32(pr, oA));
        }
        uint32_t b01[4], b23[4];
        int prB = (tb << 5) + rofsB;
        ldsm4(b01, Bb + sl32(prB, oB));          // j=0 (b0,b1), j=1 (b0,b1)
        ldsm4(b23, Bb + sl32(prB + 16, oB));     // j=2, j=3
#pragma unroll
        for (int mt = 0; mt < 4; mt++) {
            mma_fp16(acc[mt][0], af[mt], b01 + 0);
            mma_fp16(acc[mt][1], af[mt], b01 + 2);
            mma_fp16(acc[mt][2], af[mt], b23 + 0);
            mma_fp16(acc[mt][3], af[mt], b23 + 2);
        }
    };

    stage_copy(0, 0);
    CP_COMMIT();

#pragma unroll 1
    for (int s = 0; s < NS; s++) {
        __syncthreads();                 // compute(s-1) done -> buffer (s+1)&1 free
        if (s + 1 < NS) stage_copy(s + 1, (s + 1) & 1);
        CP_COMMIT();
        CP_WAIT1();                      // stage s deposits landed (this thread)
        __syncthreads();                 // all deposits visible

        uint32_t Ab = sb0 + (uint32_t)((s & 1) * BUF);
        uint32_t Bb = Ab + APL;

        if (CONV == 2 && s >= NMAIN) {
            bundle(Ab, Bb, 1, 1, 0);
        } else {
#pragma unroll
            for (int kh = 0; kh < 3; kh++)
#pragma unroll
                for (int kw = 0; kw < 3; kw++)
                    bundle(Ab, Bb, kh, kw, kh * 3 + kw);
        }
    }

    // ---- epilogue ----
    float bb0[4], bb1[4];
#pragma unroll
    for (int j = 0; j < 4; j++) {
        int co = 8 * j + 2 * lc;
        bb0[j] = bias0[co]     + ((CONV == 2) ? bias1[co]     : 0.f);
        bb1[j] = bias0[co + 1] + ((CONV == 2) ? bias1[co + 1] : 0.f);
    }

#pragma unroll
    for (int mt = 0; mt < 4; mt++) {
        int h = 4 * wid + mt;
#pragma unroll
        for (int rr = 0; rr < 2; rr++) {
            int w = lr + 8 * rr;
            if (CONV == 1) {
                size_t ridx = bOff + (size_t)(t + 1) * C18 + (d + 1) * S18 + (h + 1) * 18 + (w + 1);
                uint32_t* oh = (uint32_t*)(outH + ridx * 32);
#pragma unroll
                for (int j = 0; j < 4; j++) {
                    float v0 = fmaxf(acc[mt][j][rr * 2 + 0] + bb0[j], 0.f);
                    float v1 = fmaxf(acc[mt][j][rr * 2 + 1] + bb1[j], 0.f);
                    oh[4 * j + lc] = pack_hf(__float2half_rn(v0), __float2half_rn(v1));
                }
            } else {
                size_t obase = ((size_t)b * 32) << 16;
                int opos = (t << 12) + (d << 8) + (h << 4) + w;
#pragma unroll
                for (int j = 0; j < 4; j++) {
                    int co = 8 * j + 2 * lc;
                    float v0 = fmaxf(acc[mt][j][rr * 2 + 0] + bb0[j], 0.f);
                    float v1 = fmaxf(acc[mt][j][rr * 2 + 1] + bb1[j], 0.f);
                    outF[obase + (((size_t)co) << 16) + opos]       = v0;
                    outF[obase + (((size_t)(co + 1)) << 16) + opos] = v1;
                }
            }
        }
    }
}

// ---------------------------------------------------------------------------
extern "C" void kernel_launch(void* const* d_in, const int* in_sizes, int n_in,
                              void* d_out, int out_size)
{
    const float* x1   = (const float*)d_in[0];
    const float* x2   = (const float*)d_in[1];
    const float* up_w = (const float*)d_in[2];
    const float* up_b = (const float*)d_in[3];
    const float* w1   = (const float*)d_in[4];
    const float* b1   = (const float*)d_in[5];
    const float* w2   = (const float*)d_in[6];
    const float* b2   = (const float*)d_in[7];
    const float* w3   = (const float*)d_in[8];
    const float* b3   = (const float*)d_in[9];
    float* out = (float*)d_out;

    __half *xcF, *y1F, *w1F, *w2F, *w3F;
    cudaGetSymbolAddress((void**)&xcF, g_xcF);
    cudaGetSymbolAddress((void**)&y1F, g_y1F);
    cudaGetSymbolAddress((void**)&w1F, g_w1F);
    cudaGetSymbolAddress((void**)&w2F, g_w2F);
    cudaGetSymbolAddress((void**)&w3F, g_w3F);

    constexpr int SMB = 2 * (324 * 32 + 9 * 32 * 32);  // 39168 bytes
    cudaFuncSetAttribute(conv_mma<1>, cudaFuncAttributeMaxDynamicSharedMemorySize, SMB);
    cudaFuncSetAttribute(conv_mma<2>, cudaFuncAttributeMaxDynamicSharedMemorySize, SMB);

    // prep: pack (blocks 0..511) + weight repack (blocks 512..1023)
    prep_kernel<<<1024, 256>>>(x1, x2, up_w, up_b, w1, w2, w3);

    // conv1: y1 = relu(conv(xc, w1) + b1)
    conv_mma<1><<<dim3(256, 2), 128, SMB>>>(
        xcF, w1F, nullptr, nullptr,
        b1, nullptr, y1F, nullptr);

    // conv2: out = relu(conv(y1, w2) + b2 + conv1x1(xc, w3) + b3)
    conv_mma<2><<<dim3(256, 2), 128, SMB>>>(
        y1F, w2F, xcF, w3F,
        b2, b3, nullptr, out);
}